// round 6
// baseline (speedup 1.0000x reference)
#include <cuda_runtime.h>
#include <cstdint>

#define NIMG 64
#define CCH 256
#define KDIM (CCH*9)        // 2304
#define PIX 1024
#define BM 128
#define BN 128
#define BKC 16
#define KITERS (KDIM/BKC)   // 144
#define AS_STRIDE 20        // conflict-free for A fragment reads
#define BS_STRIDE 136       // conflict-free for B fragment reads

// Scratch (allocation-free rule: __device__ globals)
__device__ float g_xr[(size_t)NIMG*CCH*PIX];   // tf32-rounded x
__device__ float g_h [(size_t)NIMG*CCH*PIX];   // intermediate h (tf32-rounded)
__device__ float g_inv [2][CCH];
__device__ float g_bias[2][CCH];

__device__ __forceinline__ float tf32_rna(float x){
    float r; asm("cvt.rna.tf32.f32 %0, %1;" : "=f"(r) : "f"(x)); return r;
}

__global__ void bn_prep_kernel(const float* __restrict__ g1, const float* __restrict__ b1,
                               const float* __restrict__ rm1, const float* __restrict__ rv1,
                               const float* __restrict__ g2, const float* __restrict__ b2,
                               const float* __restrict__ rm2, const float* __restrict__ rv2){
    int i = threadIdx.x;
    if (i < CCH){
        float inv1 = g1[i]*rsqrtf(rv1[i]+1e-5f);
        g_inv[0][i]=inv1; g_bias[0][i]=b1[i]-rm1[i]*inv1;
        float inv2 = g2[i]*rsqrtf(rv2[i]+1e-5f);
        g_inv[1][i]=inv2; g_bias[1][i]=b2[i]-rm2[i]*inv2;
    }
}

__global__ void round_x_kernel(const float4* __restrict__ x){
    const int total = NIMG*CCH*PIX/4;
    float4* o = (float4*)g_xr;
    for (int i = blockIdx.x*blockDim.x + threadIdx.x; i < total; i += gridDim.x*blockDim.x){
        float4 v = x[i];
        v.x=tf32_rna(v.x); v.y=tf32_rna(v.y); v.z=tf32_rna(v.z); v.w=tf32_rna(v.w);
        o[i]=v;
    }
}

__device__ __forceinline__ void cp_async16(uint32_t s, const float* g){
    asm volatile("cp.async.ca.shared.global [%0], [%1], 16;\n" :: "r"(s), "l"(g));
}
__device__ __forceinline__ void cp_async4z(uint32_t s, const float* g, bool ok){
    int sz = ok ? 4 : 0;   // src-size 0 -> zero-fill, src not dereferenced
    asm volatile("cp.async.ca.shared.global [%0], [%1], 4, %2;\n" :: "r"(s), "l"(g), "r"(sz));
}
__device__ __forceinline__ void cp_commit(){ asm volatile("cp.async.commit_group;\n"); }
__device__ __forceinline__ void cp_wait0(){ asm volatile("cp.async.wait_group 0;\n"); }

__device__ __forceinline__ void mma_tf32(float* c, const uint32_t* a, const uint32_t* b){
    asm volatile("mma.sync.aligned.m16n8k8.row.col.f32.tf32.tf32.f32 "
        "{%0,%1,%2,%3}, {%4,%5,%6,%7}, {%8,%9}, {%0,%1,%2,%3};\n"
        : "+f"(c[0]), "+f"(c[1]), "+f"(c[2]), "+f"(c[3])
        : "r"(a[0]), "r"(a[1]), "r"(a[2]), "r"(a[3]), "r"(b[0]), "r"(b[1]));
}

// MODE 0: conv1: B = g_xr, out = g_h (BN1 + ReLU + tf32 round)
// MODE 1: conv2: B = g_h,  out = dout (BN2 + residual add + ReLU)
template<int MODE>
__global__ __launch_bounds__(256, 2)
void conv_kernel(const float* __restrict__ Wt, const float* __restrict__ resid,
                 float* __restrict__ dout){
    __shared__ float As[2][BM][AS_STRIDE];
    __shared__ float Bs[2][BKC][BS_STRIDE];

    const float* __restrict__ Bsrc = (MODE==0) ? g_xr : g_h;
    float* __restrict__ out = (MODE==0) ? g_h : dout;

    const int tid  = threadIdx.x;
    const int lane = tid & 31;
    const int warp = tid >> 5;
    const int qg = lane >> 2;     // octet group 0..7
    const int qt = lane & 3;      // 0..3
    const int wm = warp & 1;      // 2 warps along M
    const int wn = warp >> 1;     // 4 warps along N
    const int n   = blockIdx.z;
    const int co0 = blockIdx.y * BM;
    const int p0  = blockIdx.x * BN;

    // ---- A loader (weights, row-major [Cout][2304]) : 2x 16B cp.async per chunk ----
    const int a_m  = tid >> 1;
    const int a_k8 = (tid & 1) * 8;
    const float* a_g = Wt + (size_t)(co0 + a_m)*KDIM + a_k8;
    uint32_t a_s[2];
    a_s[0] = (uint32_t)__cvta_generic_to_shared(&As[0][a_m][a_k8]);
    a_s[1] = (uint32_t)__cvta_generic_to_shared(&As[1][a_m][a_k8]);

    // ---- B loader (im2col gather) : 8x 4B cp.async per chunk ----
    const int b_k  = tid >> 4;            // 0..15 (k within chunk)
    const int b_p  = (tid & 15) << 3;     // 0..120 (pixel within tile)
    const int b_h  = (p0 >> 5) + (b_p >> 5);  // image row (pre-offset); tile = 4 rows
    const int b_w0 = b_p & 31;
    uint32_t b_s[2];
    b_s[0] = (uint32_t)__cvta_generic_to_shared(&Bs[0][b_k][b_p]);
    b_s[1] = (uint32_t)__cvta_generic_to_shared(&Bs[1][b_k][b_p]);

    float acc[4][4][4];
    #pragma unroll
    for (int i=0;i<4;i++)
        #pragma unroll
        for (int j=0;j<4;j++)
            #pragma unroll
            for (int r=0;r<4;r++) acc[i][j][r] = 0.0f;

    auto LOAD = [&](int it, int buf){
        const int kb = it * BKC;
        cp_async16(a_s[buf],      a_g + kb);
        cp_async16(a_s[buf] + 16, a_g + kb + 4);
        const int kg  = kb + b_k;
        const int cin = kg / 9;
        const int rr  = kg - cin*9;
        const int dh  = rr / 3;
        const int dw  = rr - dh*3;
        const int hh  = b_h + dh - 1;
        const bool hok = ((unsigned)hh < 32u);
        const float* src = Bsrc + (((size_t)n*CCH + cin)*32 + hh)*32;
        #pragma unroll
        for (int pp=0; pp<8; pp++){
            const int wv = b_w0 + dw - 1 + pp;
            cp_async4z(b_s[buf] + pp*4, src + wv, hok && ((unsigned)wv < 32u));
        }
        cp_commit();
    };

    auto COMPUTE = [&](int buf){
        #pragma unroll
        for (int ks=0; ks<2; ks++){
            uint32_t a[4][4], b[4][2];
            const int kk = ks*8 + qt;
            #pragma unroll
            for (int mt=0; mt<4; mt++){
                const int m = wm*64 + mt*16 + qg;
                a[mt][0] = __float_as_uint(As[buf][m  ][kk  ]);
                a[mt][1] = __float_as_uint(As[buf][m+8][kk  ]);
                a[mt][2] = __float_as_uint(As[buf][m  ][kk+4]);
                a[mt][3] = __float_as_uint(As[buf][m+8][kk+4]);
            }
            #pragma unroll
            for (int nt=0; nt<4; nt++){
                const int cb = wn*32 + nt*8 + qg;
                b[nt][0] = __float_as_uint(Bs[buf][kk  ][cb]);
                b[nt][1] = __float_as_uint(Bs[buf][kk+4][cb]);
            }
            #pragma unroll
            for (int mt=0; mt<4; mt++)
                #pragma unroll
                for (int nt=0; nt<4; nt++)
                    mma_tf32(acc[mt][nt], a[mt], b[nt]);
        }
    };

    LOAD(0, 0);
    #pragma unroll 1
    for (int it=0; it<KITERS; it++){
        const int buf = it & 1;
        cp_wait0();
        __syncthreads();
        if (it + 1 < KITERS) LOAD(it+1, buf^1);
        COMPUTE(buf);
    }

    // ---- fused epilogue ----
    const float* __restrict__ inv  = g_inv[MODE];
    const float* __restrict__ bias = g_bias[MODE];
    #pragma unroll
    for (int mt=0; mt<4; mt++){
        const int co = co0 + wm*64 + mt*16 + qg;
        const float i0 = inv[co],   s0 = bias[co];
        const float i1 = inv[co+8], s1 = bias[co+8];
        #pragma unroll
        for (int nt=0; nt<4; nt++){
            const int p = p0 + wn*32 + nt*8 + 2*qt;
            const size_t o0 = ((size_t)n*CCH + co)*PIX + p;
            const size_t o1 = o0 + (size_t)8*PIX;
            float v0 = fmaf(acc[mt][nt][0], i0, s0);
            float v1 = fmaf(acc[mt][nt][1], i0, s0);
            float v2 = fmaf(acc[mt][nt][2], i1, s1);
            float v3 = fmaf(acc[mt][nt][3], i1, s1);
            if (MODE == 0){
                v0 = tf32_rna(fmaxf(v0, 0.0f));
                v1 = tf32_rna(fmaxf(v1, 0.0f));
                v2 = tf32_rna(fmaxf(v2, 0.0f));
                v3 = tf32_rna(fmaxf(v3, 0.0f));
            } else {
                const float2 r0 = *(const float2*)(resid + o0);
                const float2 r1 = *(const float2*)(resid + o1);
                v0 = fmaxf(r0.x + v0, 0.0f);
                v1 = fmaxf(r0.y + v1, 0.0f);
                v2 = fmaxf(r1.x + v2, 0.0f);
                v3 = fmaxf(r1.y + v3, 0.0f);
            }
            float2 w0; w0.x = v0; w0.y = v1;
            float2 w1; w1.x = v2; w1.y = v3;
            *(float2*)(out + o0) = w0;
            *(float2*)(out + o1) = w1;
        }
    }
}

extern "C" void kernel_launch(void* const* d_in, const int* in_sizes, int n_in,
                              void* d_out, int out_size){
    const float* x   = (const float*)d_in[0];
    const float* w1  = (const float*)d_in[1];
    const float* g1  = (const float*)d_in[2];
    const float* b1  = (const float*)d_in[3];
    const float* rm1 = (const float*)d_in[4];
    const float* rv1 = (const float*)d_in[5];
    const float* w2  = (const float*)d_in[6];
    const float* g2  = (const float*)d_in[7];
    const float* b2  = (const float*)d_in[8];
    const float* rm2 = (const float*)d_in[9];
    const float* rv2 = (const float*)d_in[10];
    float* out = (float*)d_out;

    bn_prep_kernel<<<1, CCH>>>(g1,b1,rm1,rv1,g2,b2,rm2,rv2);
    round_x_kernel<<<2048, 256>>>((const float4*)x);

    dim3 grid(PIX/BN, CCH/BM, NIMG);   // (8, 2, 64)
    conv_kernel<0><<<grid, 256>>>(w1, nullptr, nullptr);
    conv_kernel<1><<<grid, 256>>>(w2, x, out);
}